// round 1
// baseline (speedup 1.0000x reference)
#include <cuda_runtime.h>
#include <math.h>
#include <stdint.h>

#define BB     32
#define NN     8732
#define NCLS   20
#define DCOL   33          // NCLS + 13
#define NMSMAX 100
#define TOPK   200
#define CONF_T 0.01f
#define IOU_T  0.45f
#define NMS_THREADS 256
#define CHUNK  35          // ceil(8732/256)
#define TILE   128
#define NTILES ((NN + TILE - 1) / TILE)   // 69

// ---------------- scratch (device globals; no runtime alloc) ----------------
__device__ float  g_scores[(size_t)BB * NCLS * NN];   // thresholded, [B,C,N]
__device__ float4 g_boxes [(size_t)BB * NN];          // decoded boxes [B,N]
__device__ int    g_sel   [BB * NCLS * NMSMAX];
__device__ int    g_val   [BB * NCLS * NMSMAX];

// ---------------- phase 1: decode + score transpose/threshold ---------------
__global__ void __launch_bounds__(256) decode_kernel(const float* __restrict__ y)
{
    __shared__ float sh[TILE * DCOL];
    int blk = blockIdx.x;
    int b   = blk / NTILES;
    int t   = blk % NTILES;
    int n0  = t * TILE;
    int count = min(TILE, NN - n0);

    const float* src = y + ((size_t)b * NN + n0) * DCOL;
    int total = count * DCOL;
    for (int i = threadIdx.x; i < total; i += blockDim.x) sh[i] = src[i];
    __syncthreads();

    // scores -> [B,C,N] with threshold
    for (int k = threadIdx.x; k < NCLS * count; k += blockDim.x) {
        int c  = k / count;
        int nn = k - c * count;
        float s = sh[nn * DCOL + 1 + c];
        g_scores[((size_t)(b * NCLS + c)) * NN + n0 + nn] = (s > CONF_T) ? s : -INFINITY;
    }
    // boxes
    if (threadIdx.x < count) {
        const float* r = sh + threadIdx.x * DCOL;
        float cx_p = r[21], cy_p = r[22], w_p = r[23], h_p = r[24];
        float xa1  = r[25], ya1  = r[26], xa2 = r[27], ya2 = r[28];
        float vcx  = r[29], vcy  = r[30], vw  = r[31], vh  = r[32];
        float w_a = xa2 - xa1, h_a = ya2 - ya1;
        float cx_a = (xa2 + xa1) * 0.5f, cy_a = (ya2 + ya1) * 0.5f;
        float cx = cx_p * vcx * w_a + cx_a;
        float cy = cy_p * vcy * h_a + cy_a;
        float w  = expf(w_p * vw) * w_a;
        float h  = expf(h_p * vh) * h_a;
        float4 o;
        o.x = (cx - 0.5f * w) * 512.0f;
        o.y = (cy - 0.5f * h) * 512.0f;
        o.z = (cx + 0.5f * w) * 512.0f;
        o.w = (cy + 0.5f * h) * 512.0f;
        g_boxes[(size_t)b * NN + n0 + threadIdx.x] = o;
    }
}

// ---------------- phase 2: pop-max greedy NMS, one CTA per (b,c) ------------
__global__ void __launch_bounds__(NMS_THREADS) nms_kernel()
{
    const int bc = blockIdx.x;
    const int b  = bc / NCLS;
    const float*  sc = g_scores + (size_t)bc * NN;
    const float4* bx = g_boxes  + (size_t)b  * NN;

    __shared__ float s_sc[NN];
    __shared__ float s_lval[NMS_THREADS];
    __shared__ int   s_lidx[NMS_THREADS];
    __shared__ float s_kx1[NMSMAX], s_ky1[NMSMAX], s_kx2[NMSMAX], s_ky2[NMSMAX], s_ka[NMSMAX];
    __shared__ int   s_ns;
    __shared__ float s_mval;
    __shared__ int   s_midx;

    const int tid = threadIdx.x;
    for (int i = tid; i < NN; i += NMS_THREADS) s_sc[i] = sc[i];
    if (tid == 0) s_ns = 0;
    __syncthreads();

    {   // initial per-thread chunk maxima
        int lo = tid * CHUNK, hi = min(lo + CHUNK, NN);
        float bv = -INFINITY; int bi = 0x7FFFFFFF;
        for (int i = lo; i < hi; ++i) {
            float v = s_sc[i];
            if (v > bv || (v == bv && i < bi)) { bv = v; bi = i; }
        }
        s_lval[tid] = bv; s_lidx[tid] = bi;
    }
    __syncthreads();

    int fill = 0;
    int it = 0;
    while (true) {
        // phase A: global argmax reduction (warp 0)
        if (tid < 32) {
            float bv = -INFINITY; int bi = 0x7FFFFFFF;
#pragma unroll
            for (int k = 0; k < NMS_THREADS / 32; ++k) {
                int idx = tid + k * 32;
                float v = s_lval[idx]; int ix = s_lidx[idx];
                if (v > bv || (v == bv && ix < bi)) { bv = v; bi = ix; }
            }
#pragma unroll
            for (int off = 16; off > 0; off >>= 1) {
                float ov = __shfl_down_sync(0xFFFFFFFFu, bv, off);
                int   oi = __shfl_down_sync(0xFFFFFFFFu, bi, off);
                if (ov > bv || (ov == bv && oi < bi)) { bv = ov; bi = oi; }
            }
            if (tid == 0) { s_mval = bv; s_midx = bi; }
        }
        __syncthreads();

        float mval = s_mval;
        int   midx = s_midx;
        if (it == 0) fill = midx;           // == order[0] (first global argmax)
        if (mval == -INFINITY) break;       // pool exhausted

        int ns = s_ns;
        // phase B (concurrent): warp0 kept-check + state; one other thread removes midx
        if (tid < 32) {
            float4 bb = __ldg(&bx[midx]);
            float ax = fmaxf(bb.z - bb.x, 0.0f) * fmaxf(bb.w - bb.y, 0.0f);
            int sup = 0;
            for (int k = tid; k < ns; k += 32) {
                float ix1 = fmaxf(bb.x, s_kx1[k]);
                float iy1 = fmaxf(bb.y, s_ky1[k]);
                float ix2 = fminf(bb.z, s_kx2[k]);
                float iy2 = fminf(bb.w, s_ky2[k]);
                float inter = fmaxf(ix2 - ix1, 0.0f) * fmaxf(iy2 - iy1, 0.0f);
                float iou = inter / (ax + s_ka[k] - inter + 1e-9f);
                sup |= (iou > IOU_T);
            }
            sup = __any_sync(0xFFFFFFFFu, sup);
            if (tid == 0 && !sup) {
                s_kx1[ns] = bb.x; s_ky1[ns] = bb.y;
                s_kx2[ns] = bb.z; s_ky2[ns] = bb.w; s_ka[ns] = ax;
                g_sel[bc * NMSMAX + ns] = midx;
                g_val[bc * NMSMAX + ns] = 1;
                s_ns = ns + 1;
            }
        } else {
            int owner = midx / CHUNK;
            int exec  = 32 + (owner % (NMS_THREADS - 32));
            if (tid == exec) {
                s_sc[midx] = -INFINITY;
                int lo = owner * CHUNK, hi = min(lo + CHUNK, NN);
                float bv = -INFINITY; int bi = 0x7FFFFFFF;
                for (int i = lo; i < hi; ++i) {
                    float v = s_sc[i];
                    if (v > bv || (v == bv && i < bi)) { bv = v; bi = i; }
                }
                s_lval[owner] = bv; s_lidx[owner] = bi;
            }
        }
        __syncthreads();
        if (s_ns >= NMSMAX) break;
        ++it;
    }

    int ns = s_ns;
    for (int j = ns + tid; j < NMSMAX; j += NMS_THREADS) {
        g_sel[bc * NMSMAX + j] = fill;
        g_val[bc * NMSMAX + j] = 0;
    }
}

// ---------------- phase 3: per-batch top-200 + output assembly --------------
__device__ __forceinline__ unsigned fmap(float f) {
    unsigned u = __float_as_uint(f);
    return (u & 0x80000000u) ? ~u : (u | 0x80000000u);
}
__device__ __forceinline__ float funmap(unsigned u) {
    return __uint_as_float((u & 0x80000000u) ? (u & 0x7FFFFFFFu) : ~u);
}

__global__ void __launch_bounds__(1024) topk_kernel(float* __restrict__ out)
{
    const int b   = blockIdx.x;
    const int tid = threadIdx.x;
    __shared__ unsigned long long keys[2048];

    for (int k = tid; k < 2048; k += 1024) {
        unsigned long long key = 0ull;
        if (k < NCLS * NMSMAX) {
            int c = k / NMSMAX, i = k % NMSMAX;
            int base = (b * NCLS + c) * NMSMAX + i;
            float s = -INFINITY;
            if (g_val[base]) {
                int si = g_sel[base];
                s = g_scores[((size_t)(b * NCLS + c)) * NN + si];
            }
            key = ((unsigned long long)fmap(s) << 32) | (unsigned)(0xFFFFFFFFu - (unsigned)k);
        }
        keys[k] = key;
    }
    __syncthreads();

    // bitonic sort descending, 2048 keys
    for (int ks = 2; ks <= 2048; ks <<= 1) {
        for (int j = ks >> 1; j > 0; j >>= 1) {
#pragma unroll 2
            for (int i = tid; i < 2048; i += 1024) {
                int ixj = i ^ j;
                if (ixj > i) {
                    unsigned long long a = keys[i], q = keys[ixj];
                    bool desc = ((i & ks) == 0);
                    if (desc ? (a < q) : (a > q)) { keys[i] = q; keys[ixj] = a; }
                }
            }
            __syncthreads();
        }
    }

    if (tid < TOPK) {
        unsigned long long key = keys[tid];
        unsigned flat = 0xFFFFFFFFu - (unsigned)(key & 0xFFFFFFFFu);
        float s = funmap((unsigned)(key >> 32));
        int c = flat / NMSMAX, i = flat % NMSMAX;
        int base = (b * NCLS + c) * NMSMAX + i;
        float* o = out + ((size_t)b * TOPK + tid) * 6;
        if (g_val[base]) {
            float4 box = g_boxes[(size_t)b * NN + g_sel[base]];
            o[0] = (float)c + 1.0f; o[1] = s;
            o[2] = box.x; o[3] = box.y; o[4] = box.z; o[5] = box.w;
        } else {
            o[0] = 1.0f; o[1] = 0.0f; o[2] = 0.0f; o[3] = 0.0f; o[4] = 0.0f; o[5] = 0.0f;
        }
    }
}

// -----------------------------------------------------------------------------
extern "C" void kernel_launch(void* const* d_in, const int* in_sizes, int n_in,
                              void* d_out, int out_size)
{
    const float* y = (const float*)d_in[0];
    float* out = (float*)d_out;
    decode_kernel<<<BB * NTILES, 256>>>(y);
    nms_kernel<<<BB * NCLS, NMS_THREADS>>>();
    topk_kernel<<<BB, 1024>>>(out);
}

// round 2
// speedup vs baseline: 1.1476x; 1.1476x over previous
#include <cuda_runtime.h>
#include <math.h>
#include <stdint.h>

#define BB     32
#define NN     8732
#define NCLS   20
#define DCOL   33          // NCLS + 13
#define NMSMAX 100
#define TOPK   200
#define CONF_T 0.01f
#define IOU_T  0.45f
#define TILE   128
#define NTILES ((NN + TILE - 1) / TILE)   // 69
#define NMS_THREADS 256
#define CAND_CAP 1024
#define CAND_TARGET 384

// ---------------- scratch (device globals; no runtime alloc) ----------------
__device__ float  g_scores[(size_t)BB * NCLS * NN];   // thresholded, [B,C,N]
__device__ float4 g_boxes [(size_t)BB * NN];          // decoded boxes [B,N]
__device__ int    g_sel   [BB * NCLS * NMSMAX];
__device__ int    g_val   [BB * NCLS * NMSMAX];

// ---------------- phase 1: decode + score transpose/threshold ---------------
__global__ void __launch_bounds__(256) decode_kernel(const float* __restrict__ y)
{
    __shared__ float sh[TILE * DCOL];
    int blk = blockIdx.x;
    int b   = blk / NTILES;
    int t   = blk % NTILES;
    int n0  = t * TILE;
    int count = min(TILE, NN - n0);

    const float* src = y + ((size_t)b * NN + n0) * DCOL;
    int total = count * DCOL;
    for (int i = threadIdx.x; i < total; i += blockDim.x) sh[i] = src[i];
    __syncthreads();

    if (count == TILE) {
        for (int k = threadIdx.x; k < NCLS * TILE; k += blockDim.x) {
            int c  = k >> 7;
            int nn = k & (TILE - 1);
            float s = sh[nn * DCOL + 1 + c];
            g_scores[((size_t)(b * NCLS + c)) * NN + n0 + nn] = (s > CONF_T) ? s : -INFINITY;
        }
    } else {
        for (int k = threadIdx.x; k < NCLS * count; k += blockDim.x) {
            int c  = k / count;
            int nn = k - c * count;
            float s = sh[nn * DCOL + 1 + c];
            g_scores[((size_t)(b * NCLS + c)) * NN + n0 + nn] = (s > CONF_T) ? s : -INFINITY;
        }
    }
    if (threadIdx.x < count) {
        const float* r = sh + threadIdx.x * DCOL;
        float cx_p = r[21], cy_p = r[22], w_p = r[23], h_p = r[24];
        float xa1  = r[25], ya1  = r[26], xa2 = r[27], ya2 = r[28];
        float vcx  = r[29], vcy  = r[30], vw  = r[31], vh  = r[32];
        float w_a = xa2 - xa1, h_a = ya2 - ya1;
        float cx_a = (xa2 + xa1) * 0.5f, cy_a = (ya2 + ya1) * 0.5f;
        float cx = cx_p * vcx * w_a + cx_a;
        float cy = cy_p * vcy * h_a + cy_a;
        float w  = expf(w_p * vw) * w_a;
        float h  = expf(h_p * vh) * h_a;
        float4 o;
        o.x = (cx - 0.5f * w) * 512.0f;
        o.y = (cy - 0.5f * h) * 512.0f;
        o.z = (cx + 0.5f * w) * 512.0f;
        o.w = (cy + 0.5f * h) * 512.0f;
        g_boxes[(size_t)b * NN + n0 + threadIdx.x] = o;
    }
}

// monotonic float -> u32 map (order preserving)
__device__ __forceinline__ unsigned fmap(float f) {
    unsigned u = __float_as_uint(f);
    return (u & 0x80000000u) ? ~u : (u | 0x80000000u);
}
__device__ __forceinline__ float funmap(unsigned u) {
    return __uint_as_float((u & 0x80000000u) ? (u & 0x7FFFFFFFu) : ~u);
}

// ---------------- phase 2: sorted-candidate greedy NMS ----------------------
// One CTA per (b,c). Histogram -> bin-group cutoff -> gather -> bitonic sort ->
// single-warp sequential greedy with kept list in registers.
__global__ void __launch_bounds__(NMS_THREADS) nms_kernel()
{
    const int bc = blockIdx.x;
    const int b  = bc / NCLS;
    const float*  sc = g_scores + (size_t)bc * NN;
    const float4* bx = g_boxes  + (size_t)b  * NN;

    __shared__ unsigned           hist[4096];          // 16 KB
    __shared__ unsigned long long cand[CAND_CAP];      // 8 KB
    __shared__ float4             cbox[CAND_CAP];      // 16 KB
    __shared__ int                s_selidx[NMSMAX];
    __shared__ int                s_cnt, s_ns, s_fill, s_lo, s_cum;

    const int tid  = threadIdx.x;
    const int lane = tid & 31;

    for (int i = tid; i < 4096; i += NMS_THREADS) hist[i] = 0;
    if (tid == 0) { s_ns = 0; s_fill = 0; }
    __syncthreads();

    // histogram of mapped scores (candidates only)
    for (int i = tid; i < NN; i += NMS_THREADS) {
        float v = sc[i];
        if (v != -INFINITY) atomicAdd(&hist[fmap(v) >> 20], 1u);
    }
    __syncthreads();

    // kept-box registers, lane-distributed (warp 0 only meaningful)
    float kx1_0=0,ky1_0=0,kx2_0=0,ky2_0=0,ka_0=0;
    float kx1_1=0,ky1_1=0,kx2_1=0,ky2_1=0,ka_1=0;
    float kx1_2=0,ky1_2=0,kx2_2=0,ky2_2=0,ka_2=0;
    float kx1_3=0,ky1_3=0,kx2_3=0,ky2_3=0,ka_3=0;
    int ns = 0;

    int curHi = 4096;        // exclusive upper bin of remaining pool
    bool firstGroup = true;

    while (true) {
        // ---- A: warp0 walks bins downward to pick group [lo, curHi) ----
        if (tid < 32) {
            int lo = curHi;
            unsigned cum = 0;
            while (lo > 0 && cum < CAND_TARGET) {
                int chunkBase = lo - 32; if (chunkBase < 0) chunkBase = 0;
                int nb = lo - chunkBase;
                int bi = lo - 1 - lane;                    // lane0 = highest bin
                unsigned h = (lane < nb) ? hist[bi] : 0u;
                unsigned p = h;
                #pragma unroll
                for (int o = 1; o < 32; o <<= 1) {
                    unsigned t2 = __shfl_up_sync(0xFFFFFFFFu, p, o);
                    if (lane >= o) p += t2;
                }
                unsigned tot = __shfl_sync(0xFFFFFFFFu, p, 31);
                if (cum + tot <= CAND_CAP) {
                    cum += tot; lo = chunkBase;
                } else {
                    unsigned ok = __ballot_sync(0xFFFFFFFFu, cum + p <= (unsigned)CAND_CAP);
                    int k = __popc(ok);
                    if (k == 0 && cum == 0) k = 1;         // single huge bin: take it (clamped)
                    if (k > 0) {
                        unsigned add = __shfl_sync(0xFFFFFFFFu, p, k - 1);
                        cum += add; lo -= k;
                        if (cum > CAND_CAP) cum = CAND_CAP;
                    }
                    break;
                }
            }
            if (lane == 0) { s_lo = lo; s_cum = (int)cum; s_cnt = 0; }
        }
        __syncthreads();
        int binLo = s_lo;
        if (s_cum == 0) break;                 // pool exhausted

        // ---- B: gather candidates in [binLo, curHi) ----
        for (int i = tid; i < NN; i += NMS_THREADS) {
            float v = sc[i];
            if (v != -INFINITY) {
                unsigned m = fmap(v);
                int bin = (int)(m >> 20);
                if (bin >= binLo && bin < curHi) {
                    int p = atomicAdd(&s_cnt, 1);
                    if (p < CAND_CAP)
                        cand[p] = ((unsigned long long)m << 32) |
                                  (unsigned)(0xFFFFFFFFu - (unsigned)i);
                }
            }
        }
        __syncthreads();
        int cnt = min(s_cnt, CAND_CAP);

        // pad to pow2 and bitonic sort descending
        int P = 32; while (P < cnt) P <<= 1;
        for (int i = cnt + tid; i < P; i += NMS_THREADS) cand[i] = 0ull;
        __syncthreads();
        for (int ks = 2; ks <= P; ks <<= 1) {
            for (int j = ks >> 1; j > 0; j >>= 1) {
                for (int i = tid; i < P; i += NMS_THREADS) {
                    int ixj = i ^ j;
                    if (ixj > i) {
                        unsigned long long a = cand[i], q = cand[ixj];
                        bool desc = ((i & ks) == 0);
                        if (desc ? (a < q) : (a > q)) { cand[i] = q; cand[ixj] = a; }
                    }
                }
                __syncthreads();
            }
        }

        // ---- C: prefetch boxes in sorted order ----
        for (int t = tid; t < cnt; t += NMS_THREADS) {
            int idx = (int)(0xFFFFFFFFu - (unsigned)(cand[t] & 0xFFFFFFFFull));
            cbox[t] = __ldg(&bx[idx]);
        }
        if (firstGroup && tid == 0 && cnt > 0)
            s_fill = (int)(0xFFFFFFFFu - (unsigned)(cand[0] & 0xFFFFFFFFull));
        __syncthreads();
        firstGroup = false;

        // ---- D: single-warp sequential greedy ----
        if (tid < 32) {
            for (int t = 0; t < cnt && ns < NMSMAX; ++t) {
                float4 Bb = cbox[t];
                float ax = fmaxf(Bb.z - Bb.x, 0.0f) * fmaxf(Bb.w - Bb.y, 0.0f);
                int sup = 0;
                #define CHECKJ(J) \
                    if (J * 32 + lane < ns) { \
                        float ix1 = fmaxf(Bb.x, kx1_##J); \
                        float iy1 = fmaxf(Bb.y, ky1_##J); \
                        float ix2 = fminf(Bb.z, kx2_##J); \
                        float iy2 = fminf(Bb.w, ky2_##J); \
                        float inter = fmaxf(ix2 - ix1, 0.0f) * fmaxf(iy2 - iy1, 0.0f); \
                        float iou = inter / (ax + ka_##J - inter + 1e-9f); \
                        sup |= (iou > IOU_T); \
                    }
                CHECKJ(0) CHECKJ(1) CHECKJ(2) CHECKJ(3)
                #undef CHECKJ
                if (!__any_sync(0xFFFFFFFFu, sup)) {
                    if (lane == (ns & 31)) {
                        #define INSJ(J) if ((ns >> 5) == J) { \
                            kx1_##J = Bb.x; ky1_##J = Bb.y; \
                            kx2_##J = Bb.z; ky2_##J = Bb.w; ka_##J = ax; }
                        INSJ(0) INSJ(1) INSJ(2) INSJ(3)
                        #undef INSJ
                    }
                    if (lane == 0)
                        s_selidx[ns] = (int)(0xFFFFFFFFu - (unsigned)(cand[t] & 0xFFFFFFFFull));
                    ++ns;
                }
            }
            if (lane == 0) s_ns = ns;
        }
        __syncthreads();
        if (s_ns >= NMSMAX) break;
        curHi = binLo;
        if (curHi == 0) break;
    }
    __syncthreads();

    int nsf  = s_ns;
    int fill = s_fill;
    if (tid < nsf) {
        g_sel[bc * NMSMAX + tid] = s_selidx[tid];
        g_val[bc * NMSMAX + tid] = 1;
    }
    for (int j = nsf + tid; j < NMSMAX; j += NMS_THREADS) {
        g_sel[bc * NMSMAX + j] = fill;
        g_val[bc * NMSMAX + j] = 0;
    }
}

// ---------------- phase 3: per-batch top-200 + output assembly --------------
__global__ void __launch_bounds__(1024) topk_kernel(float* __restrict__ out)
{
    const int b   = blockIdx.x;
    const int tid = threadIdx.x;
    __shared__ unsigned long long keys[2048];

    for (int k = tid; k < 2048; k += 1024) {
        unsigned long long key = 0ull;
        if (k < NCLS * NMSMAX) {
            int c = k / NMSMAX, i = k % NMSMAX;
            int base = (b * NCLS + c) * NMSMAX + i;
            float s = -INFINITY;
            if (g_val[base]) {
                int si = g_sel[base];
                s = g_scores[((size_t)(b * NCLS + c)) * NN + si];
            }
            key = ((unsigned long long)fmap(s) << 32) | (unsigned)(0xFFFFFFFFu - (unsigned)k);
        }
        keys[k] = key;
    }
    __syncthreads();

    for (int ks = 2; ks <= 2048; ks <<= 1) {
        for (int j = ks >> 1; j > 0; j >>= 1) {
#pragma unroll 2
            for (int i = tid; i < 2048; i += 1024) {
                int ixj = i ^ j;
                if (ixj > i) {
                    unsigned long long a = keys[i], q = keys[ixj];
                    bool desc = ((i & ks) == 0);
                    if (desc ? (a < q) : (a > q)) { keys[i] = q; keys[ixj] = a; }
                }
            }
            __syncthreads();
        }
    }

    if (tid < TOPK) {
        unsigned long long key = keys[tid];
        unsigned flat = 0xFFFFFFFFu - (unsigned)(key & 0xFFFFFFFFull);
        float s = funmap((unsigned)(key >> 32));
        int c = flat / NMSMAX, i = flat % NMSMAX;
        int base = (b * NCLS + c) * NMSMAX + i;
        float* o = out + ((size_t)b * TOPK + tid) * 6;
        if (g_val[base]) {
            float4 box = g_boxes[(size_t)b * NN + g_sel[base]];
            o[0] = (float)c + 1.0f; o[1] = s;
            o[2] = box.x; o[3] = box.y; o[4] = box.z; o[5] = box.w;
        } else {
            o[0] = 1.0f; o[1] = 0.0f; o[2] = 0.0f; o[3] = 0.0f; o[4] = 0.0f; o[5] = 0.0f;
        }
    }
}

// -----------------------------------------------------------------------------
extern "C" void kernel_launch(void* const* d_in, const int* in_sizes, int n_in,
                              void* d_out, int out_size)
{
    const float* y = (const float*)d_in[0];
    float* out = (float*)d_out;
    decode_kernel<<<BB * NTILES, 256>>>(y);
    nms_kernel<<<BB * NCLS, NMS_THREADS>>>();
    topk_kernel<<<BB, 1024>>>(out);
}

// round 3
// speedup vs baseline: 1.5672x; 1.3657x over previous
#include <cuda_runtime.h>
#include <math.h>
#include <stdint.h>

#define BB     32
#define NN     8732
#define NNP    8736          // padded to multiple of 4 for float4 loads
#define NCLS   20
#define DCOL   33
#define NMSMAX 100
#define TOPK   200
#define CONF_T 0.01f
#define IOU_T  0.45f
#define TILE   128
#define NTILES ((NN + TILE - 1) / TILE)   // 69
#define NMS_THREADS 256
#define CAP    512

// ---------------- scratch ----------------
__device__ __align__(16) float  g_scores[(size_t)BB * NCLS * NNP];  // thresholded [B,C,NNP]
__device__ float4 g_boxes   [(size_t)BB * NN];
__device__ int    g_sel     [BB * NCLS * NMSMAX];
__device__ int    g_val     [BB * NCLS * NMSMAX];
__device__ float  g_selscore[BB * NCLS * NMSMAX];
__device__ float4 g_selbox  [BB * NCLS * NMSMAX];

// monotonic float <-> u32 order-preserving map
__device__ __forceinline__ unsigned fmap(float f) {
    unsigned u = __float_as_uint(f);
    return (u & 0x80000000u) ? ~u : (u | 0x80000000u);
}
__device__ __forceinline__ float funmap(unsigned u) {
    return __uint_as_float((u & 0x80000000u) ? (u & 0x7FFFFFFFu) : ~u);
}

// ---------------- phase 1: decode + transpose/threshold ---------------
__global__ void __launch_bounds__(256) decode_kernel(const float* __restrict__ y)
{
    __shared__ float sh[TILE * DCOL];
    int blk = blockIdx.x;
    int b   = blk / NTILES;
    int t   = blk % NTILES;
    int n0  = t * TILE;
    int count = min(TILE, NN - n0);

    const float* src = y + ((size_t)b * NN + n0) * DCOL;
    int total = count * DCOL;
    for (int i = threadIdx.x; i < total; i += blockDim.x) sh[i] = src[i];
    __syncthreads();

    if (count == TILE) {
        for (int k = threadIdx.x; k < NCLS * TILE; k += blockDim.x) {
            int c  = k >> 7;
            int nn = k & (TILE - 1);
            float s = sh[nn * DCOL + 1 + c];
            g_scores[((size_t)(b * NCLS + c)) * NNP + n0 + nn] = (s > CONF_T) ? s : -INFINITY;
        }
    } else {
        for (int k = threadIdx.x; k < NCLS * count; k += blockDim.x) {
            int c  = k / count;
            int nn = k - c * count;
            float s = sh[nn * DCOL + 1 + c];
            g_scores[((size_t)(b * NCLS + c)) * NNP + n0 + nn] = (s > CONF_T) ? s : -INFINITY;
        }
        // pad tail [NN, NNP) with -inf for vectorized NMS gather
        for (int k = threadIdx.x; k < NCLS * (NNP - NN); k += blockDim.x) {
            int c  = k >> 2;
            int nn = k & 3;
            g_scores[((size_t)(b * NCLS + c)) * NNP + NN + nn] = -INFINITY;
        }
    }
    if (threadIdx.x < count) {
        const float* r = sh + threadIdx.x * DCOL;
        float cx_p = r[21], cy_p = r[22], w_p = r[23], h_p = r[24];
        float xa1  = r[25], ya1  = r[26], xa2 = r[27], ya2 = r[28];
        float vcx  = r[29], vcy  = r[30], vw  = r[31], vh  = r[32];
        float w_a = xa2 - xa1, h_a = ya2 - ya1;
        float cx_a = (xa2 + xa1) * 0.5f, cy_a = (ya2 + ya1) * 0.5f;
        float cx = cx_p * vcx * w_a + cx_a;
        float cy = cy_p * vcy * h_a + cy_a;
        float w  = expf(w_p * vw) * w_a;
        float h  = expf(h_p * vh) * h_a;
        float4 o;
        o.x = (cx - 0.5f * w) * 512.0f;
        o.y = (cy - 0.5f * h) * 512.0f;
        o.z = (cx + 0.5f * w) * 512.0f;
        o.w = (cy + 0.5f * h) * 512.0f;
        g_boxes[(size_t)b * NN + n0 + threadIdx.x] = o;
    }
}

// ---------------- phase 2: windowed-gather sorted greedy NMS ---------------
__global__ void __launch_bounds__(NMS_THREADS) nms_kernel()
{
    const int bc = blockIdx.x;
    const int b  = bc / NCLS;
    const float*  sc = g_scores + (size_t)bc * NNP;
    const float4* bx = g_boxes  + (size_t)b  * NN;

    __shared__ unsigned long long cand[CAP];   // 4 KB
    __shared__ float4             cbox[CAP];   // 8 KB
    __shared__ int s_cnt, s_ns, s_fill, s_fillset;

    const int tid  = threadIdx.x;
    const int lane = tid & 31;
    if (tid == 0) { s_ns = 0; s_fill = 0; s_fillset = 0; }

    // kept boxes lane-distributed in registers (warp 0)
    float kx1_0=0,ky1_0=0,kx2_0=0,ky2_0=0,ka_0=0;
    float kx1_1=0,ky1_1=0,kx2_1=0,ky2_1=0,ka_1=0;
    float kx1_2=0,ky1_2=0,kx2_2=0,ky2_2=0,ka_2=0;
    float kx1_3=0,ky1_3=0,kx2_3=0,ky2_3=0,ka_3=0;
    int ns = 0;

    unsigned hi = 0xFFFFFFFFu;         // exclusive upper (mapped domain)
    unsigned lo = fmap(0.975f);        // fast-path first window

    const float4* sv = (const float4*)sc;

    for (;;) {
        // ---- gather window [lo, hi), halving on overflow (exact) ----
        int cnt;
        for (;;) {
            __syncthreads();
            if (tid == 0) s_cnt = 0;
            __syncthreads();
            for (int i = tid; i < NNP / 4; i += NMS_THREADS) {
                float4 v = sv[i];
                int base = i << 2;
                #pragma unroll
                for (int k = 0; k < 4; ++k) {
                    float val = (k == 0) ? v.x : (k == 1) ? v.y : (k == 2) ? v.z : v.w;
                    if (val != -INFINITY) {
                        unsigned m = fmap(val);
                        if (m >= lo && m < hi) {
                            int p = atomicAdd(&s_cnt, 1);
                            if (p < CAP)
                                cand[p] = ((unsigned long long)m << 32) |
                                          (unsigned)(0xFFFFFFFFu - (unsigned)(base + k));
                        }
                    }
                }
            }
            __syncthreads();
            cnt = s_cnt;
            if (cnt <= CAP || hi - lo <= 1) break;
            lo = lo + ((hi - lo) >> 1);
        }
        if (cnt > CAP) cnt = CAP;

        if (cnt == 0) {
            if (lo == 0) break;        // pool exhausted
            hi = lo; lo = 0; continue;
        }

        // ---- bitonic sort descending (pad to pow2) ----
        int P = 1; while (P < cnt) P <<= 1;
        for (int i = cnt + tid; i < P; i += NMS_THREADS) cand[i] = 0ull;
        __syncthreads();
        for (int ks = 2; ks <= P; ks <<= 1) {
            for (int j = ks >> 1; j > 0; j >>= 1) {
                for (int i = tid; i < P; i += NMS_THREADS) {
                    int ixj = i ^ j;
                    if (ixj > i) {
                        unsigned long long a = cand[i], q = cand[ixj];
                        bool desc = ((i & ks) == 0);
                        if (desc ? (a < q) : (a > q)) { cand[i] = q; cand[ixj] = a; }
                    }
                }
                __syncthreads();
            }
        }

        if (tid == 0 && !s_fillset) {
            s_fillset = 1;
            s_fill = (int)(0xFFFFFFFFu - (unsigned)(cand[0] & 0xFFFFFFFFull));
        }
        // prefetch boxes in sorted order
        for (int t = tid; t < cnt; t += NMS_THREADS) {
            int idx = (int)(0xFFFFFFFFu - (unsigned)(cand[t] & 0xFFFFFFFFull));
            cbox[t] = __ldg(&bx[idx]);
        }
        __syncthreads();

        // ---- single-warp sequential greedy ----
        if (tid < 32) {
            float4 nb = cbox[0];
            for (int t = 0; t < cnt && ns < NMSMAX; ++t) {
                float4 Bb = nb;
                if (t + 1 < cnt) nb = cbox[t + 1];
                float ax = fmaxf(Bb.z - Bb.x, 0.0f) * fmaxf(Bb.w - Bb.y, 0.0f);
                int sup = 0;
                #define CHECKJ(J) \
                    if (J * 32 + lane < ns) { \
                        float ix1 = fmaxf(Bb.x, kx1_##J); \
                        float iy1 = fmaxf(Bb.y, ky1_##J); \
                        float ix2 = fminf(Bb.z, kx2_##J); \
                        float iy2 = fminf(Bb.w, ky2_##J); \
                        float inter = fmaxf(ix2 - ix1, 0.0f) * fmaxf(iy2 - iy1, 0.0f); \
                        float iou = inter / (ax + ka_##J - inter + 1e-9f); \
                        sup |= (iou > IOU_T); \
                    }
                CHECKJ(0) CHECKJ(1) CHECKJ(2) CHECKJ(3)
                #undef CHECKJ
                if (!__any_sync(0xFFFFFFFFu, sup)) {
                    if (lane == (ns & 31)) {
                        #define INSJ(J) if ((ns >> 5) == J) { \
                            kx1_##J = Bb.x; ky1_##J = Bb.y; \
                            kx2_##J = Bb.z; ky2_##J = Bb.w; ka_##J = ax; }
                        INSJ(0) INSJ(1) INSJ(2) INSJ(3)
                        #undef INSJ
                    }
                    if (lane == 0) {
                        unsigned long long key = cand[t];
                        int oi = (int)(0xFFFFFFFFu - (unsigned)(key & 0xFFFFFFFFull));
                        int o  = bc * NMSMAX + ns;
                        g_sel[o] = oi;
                        g_val[o] = 1;
                        g_selscore[o] = funmap((unsigned)(key >> 32));
                        g_selbox[o] = Bb;
                    }
                    ++ns;
                }
            }
            if (lane == 0) s_ns = ns;
        }
        __syncthreads();
        if (s_ns >= NMSMAX) break;
        if (lo == 0) break;
        hi = lo; lo = 0;
    }
    __syncthreads();

    int nsf  = s_ns;
    int fill = s_fillset ? s_fill : 0;
    for (int j = nsf + tid; j < NMSMAX; j += NMS_THREADS) {
        int o = bc * NMSMAX + j;
        g_sel[o] = fill;
        g_val[o] = 0;
        g_selscore[o] = -INFINITY;
    }
}

// ---------------- phase 3: per-batch top-200 -------------------------------
__global__ void __launch_bounds__(512) topk_kernel(float* __restrict__ out)
{
    const int b   = blockIdx.x;
    const int tid = threadIdx.x;
    __shared__ unsigned long long keys[2048];

    for (int k = tid; k < 2048; k += 512) {
        unsigned long long key = 0ull;
        if (k < NCLS * NMSMAX) {
            float s = g_selscore[b * NCLS * NMSMAX + k];   // -inf when invalid
            key = ((unsigned long long)fmap(s) << 32) | (unsigned)(0xFFFFFFFFu - (unsigned)k);
        }
        keys[k] = key;
    }
    __syncthreads();

    for (int ks = 2; ks <= 2048; ks <<= 1) {
        for (int j = ks >> 1; j > 0; j >>= 1) {
            #pragma unroll 4
            for (int i = tid; i < 2048; i += 512) {
                int ixj = i ^ j;
                if (ixj > i) {
                    unsigned long long a = keys[i], q = keys[ixj];
                    bool desc = ((i & ks) == 0);
                    if (desc ? (a < q) : (a > q)) { keys[i] = q; keys[ixj] = a; }
                }
            }
            __syncthreads();
        }
    }

    if (tid < TOPK) {
        unsigned long long key = keys[tid];
        unsigned flat = 0xFFFFFFFFu - (unsigned)(key & 0xFFFFFFFFull);
        int c = flat / NMSMAX, i = flat - c * NMSMAX;
        int base = (b * NCLS + c) * NMSMAX + i;
        float* o = out + ((size_t)b * TOPK + tid) * 6;
        if (g_val[base]) {
            float4 box = g_selbox[base];
            o[0] = (float)c + 1.0f;
            o[1] = funmap((unsigned)(key >> 32));
            o[2] = box.x; o[3] = box.y; o[4] = box.z; o[5] = box.w;
        } else {
            o[0] = 1.0f; o[1] = 0.0f; o[2] = 0.0f; o[3] = 0.0f; o[4] = 0.0f; o[5] = 0.0f;
        }
    }
}

// -----------------------------------------------------------------------------
extern "C" void kernel_launch(void* const* d_in, const int* in_sizes, int n_in,
                              void* d_out, int out_size)
{
    const float* y = (const float*)d_in[0];
    float* out = (float*)d_out;
    decode_kernel<<<BB * NTILES, 256>>>(y);
    nms_kernel<<<BB * NCLS, NMS_THREADS>>>();
    topk_kernel<<<BB, 512>>>(out);
}